// round 16
// baseline (speedup 1.0000x reference)
#include <cuda_runtime.h>
#include <cuda_fp16.h>
#include <mma.h>
#include <math.h>

using namespace nvcuda;

// ----- problem constants -----
#define BB    2
#define AA    900
#define EDD   256
#define NGRP  8
#define NCAM  6
#define NLVL  4
#define NPT   7
#define NW    1344            // NGRP*NCAM*NLVL*NPT
#define NBA   (BB*AA)         // 1800
#define MPAD  1920
#define NDESC (NCAM*NPT*NLVL) // 168
#define NBC   (BB*NCAM)       // 12

// level geometry
#define HW0 11264
#define HW1 2816
#define HW2 704
#define HW3 176
#define PB0 0
#define PB1 (NBC*HW0)
#define PB2 (PB1 + NBC*HW1)
#define PB3 (PB2 + NBC*HW2)
#define NPIX (PB3 + NBC*HW3)           // 179520

// conversion blocks: per level NBC * pixTiles(64px) * chTiles(4x64)
#define CT0 176
#define CT1 44
#define CT2 11
#define CT3 3
#define CV0 (NBC*CT0*4)
#define CV1 (NBC*CT1*4)
#define CV2 (NBC*CT2*4)
#define CV3 (NBC*CT3*4)
#define CVTOT (CV0+CV1+CV2+CV3)        // 11232

#define GEMM_BLKS ((NW/64) * (MPAD/128))   // 315
#define WOUT_BLKS 64

// ----- scratch (allocation-free: device globals; zero-initialized) -----
__device__ __align__(16) __half g_woutH[EDD * EDD];
__device__ __align__(16) float  g_w[MPAD * NW];
__device__ __align__(16) __half g_fusedH[MPAD * EDD];
__device__ __align__(16) __half g_nhwc[(size_t)NPIX * EDD];

// =====================================================================
// FC GEMM kernel (R15 verbatim): g_w = (inst+emb) @ w_fc^T, fp16 wmma,
// plus w_out fp32->fp16 conversion in tail blocks.
// =====================================================================
__global__ void __launch_bounds__(256) fc_gemm_kernel(
    const float* __restrict__ inst, const float* __restrict__ emb,
    const float* __restrict__ w_fc, const float* __restrict__ w_out)
{
    __shared__ __align__(16) __half sA[128 * 32];
    __shared__ __align__(16) __half sB[64 * 32];
    const int tid = threadIdx.x;

    if (blockIdx.x >= GEMM_BLKS) {
        int j = (blockIdx.x - GEMM_BLKS) * 256 + tid;   // float4 idx
        float4 v = *(const float4*)(w_out + (size_t)j * 4);
        __half2 h0 = __floats2half2_rn(v.x, v.y);
        __half2 h1 = __floats2half2_rn(v.z, v.w);
        uint2 o;
        o.x = *(unsigned*)&h0;
        o.y = *(unsigned*)&h1;
        *(uint2*)(g_woutH + (size_t)j * 4) = o;
        return;
    }

    const int gx = blockIdx.x % (NW / 64);
    const int gy = blockIdx.x / (NW / 64);
    const int bm0 = gy * 128;
    const int bn0 = gx * 64;
    const int wid = tid >> 5;
    const int wm  = wid & 3;
    const int wn  = wid >> 2;
    const int m0 = wm * 32;
    const int n0 = wn * 32;

    wmma::fragment<wmma::accumulator, 16, 16, 16, float> cf[2][2];
#pragma unroll
    for (int i = 0; i < 2; i++)
#pragma unroll
        for (int j = 0; j < 2; j++) wmma::fill_fragment(cf[i][j], 0.f);

    for (int kt = 0; kt < 256; kt += 32) {
#pragma unroll
        for (int s = 0; s < 4; s++) {
            int id = tid + s * 256;
            int row = id >> 3, q = id & 7;
            int m = bm0 + row;
            float4 v = make_float4(0.f, 0.f, 0.f, 0.f);
            if (m < NBA) {
                v = *(const float4*)(inst + (size_t)m * 256 + kt + q * 4);
                float4 w = *(const float4*)(emb + (size_t)m * 256 + kt + q * 4);
                v.x += w.x; v.y += w.y; v.z += w.z; v.w += w.w;
            }
            __half2* d = (__half2*)&sA[row * 32 + q * 4];
            d[0] = __floats2half2_rn(v.x, v.y);
            d[1] = __floats2half2_rn(v.z, v.w);
        }
#pragma unroll
        for (int s = 0; s < 2; s++) {
            int id = tid + s * 256;
            int row = id >> 3, q = id & 7;
            int n = bn0 + row;
            float4 v = *(const float4*)(w_fc + (size_t)n * 256 + kt + q * 4);
            __half2* d = (__half2*)&sB[row * 32 + q * 4];
            d[0] = __floats2half2_rn(v.x, v.y);
            d[1] = __floats2half2_rn(v.z, v.w);
        }
        __syncthreads();

#pragma unroll
        for (int kk = 0; kk < 2; kk++) {
            wmma::fragment<wmma::matrix_a, 16, 16, 16, __half, wmma::row_major> af[2];
            wmma::fragment<wmma::matrix_b, 16, 16, 16, __half, wmma::col_major> bf[2];
#pragma unroll
            for (int i = 0; i < 2; i++)
                wmma::load_matrix_sync(af[i], sA + (m0 + i * 16) * 32 + kk * 16, 32);
#pragma unroll
            for (int j = 0; j < 2; j++)
                wmma::load_matrix_sync(bf[j], sB + (n0 + j * 16) * 32 + kk * 16, 32);
#pragma unroll
            for (int i = 0; i < 2; i++)
#pragma unroll
                for (int j = 0; j < 2; j++)
                    wmma::mma_sync(cf[i][j], af[i], bf[j], cf[i][j]);
        }
        __syncthreads();
    }
#pragma unroll
    for (int i = 0; i < 2; i++)
#pragma unroll
        for (int j = 0; j < 2; j++)
            wmma::store_matrix_sync(g_w + (size_t)(bm0 + m0 + i * 16) * NW + bn0 + n0 + j * 16,
                                    cf[i][j], NW, wmma::mem_row_major);
}

// =====================================================================
// Conversion kernel (R15/R10 verbatim): NCHW fp32 -> NHWC fp16,
// 64ch x 64px tile per block, 256 threads.
// =====================================================================
__global__ void __launch_bounds__(256) conv_kernel(
    const float* __restrict__ f0, const float* __restrict__ f1,
    const float* __restrict__ f2, const float* __restrict__ f3)
{
    __shared__ float t[64][65];
    const int tid = threadIdx.x;

    int cb = blockIdx.x;
    const float* fin; int HWl, tilesHW, pbase;
    if (cb < CV0)               { fin = f0; HWl = HW0; tilesHW = CT0; pbase = PB0; }
    else if ((cb -= CV0) < CV1) { fin = f1; HWl = HW1; tilesHW = CT1; pbase = PB1; }
    else if ((cb -= CV1) < CV2) { fin = f2; HWl = HW2; tilesHW = CT2; pbase = PB2; }
    else       { cb -= CV2;       fin = f3; HWl = HW3; tilesHW = CT3; pbase = PB3; }
    const int nt  = tilesHW * 4;
    const int bc  = cb / nt;
    const int r   = cb % nt;
    const int hw0 = (r >> 2) * 64;
    const int c0  = (r & 3) * 64;

    const float* ip = fin + (size_t)bc * 256 * HWl;
#pragma unroll
    for (int s = 0; s < 4; s++) {
        int id = tid + s * 256;
        int row = id >> 4, q = id & 15;
        int hw = hw0 + q * 4;
        if (hw < HWl) {
            float4 v = __ldcs((const float4*)(ip + (size_t)(c0 + row) * HWl + hw));
            t[row][q * 4 + 0] = v.x;
            t[row][q * 4 + 1] = v.y;
            t[row][q * 4 + 2] = v.z;
            t[row][q * 4 + 3] = v.w;
        }
    }
    __syncthreads();
    __half* op = g_nhwc + ((size_t)(pbase + bc * HWl)) * 256;
#pragma unroll
    for (int s = 0; s < 4; s++) {
        int id = tid + s * 256;
        int px = id >> 4, qc = id & 15;
        int hw = hw0 + px;
        if (hw < HWl) {
            __half2 h0 = __floats2half2_rn(t[qc * 4 + 0][px], t[qc * 4 + 1][px]);
            __half2 h1 = __floats2half2_rn(t[qc * 4 + 2][px], t[qc * 4 + 3][px]);
            uint2 o;
            o.x = *(unsigned*)&h0;
            o.y = *(unsigned*)&h1;
            *(uint2*)(op + (size_t)hw * 256 + c0 + qc * 4) = o;
        }
    }
}

// =====================================================================
// Fused aggregation: 128 threads / 4 warps; lane covers 8 channels
// (uint4 gathers); warps split the descriptor list 4 ways; gather
// loop manually unrolled 2x (both iterations' loads issued first ->
// MLP 8) with a 4-way smem partial reduce at the end.
// =====================================================================
__global__ void __launch_bounds__(128) agg_kernel(
    const float* __restrict__ anchor, const float* __restrict__ proj,
    const float* __restrict__ wh, const float* __restrict__ b_fc)
{
    __shared__ float  s_w[NW];
    __shared__ float  s_uv[NCAM * NPT][2];
    __shared__ int4   s_dA[NDESC];
    __shared__ float4 s_dW[NDESC];
    __shared__ int    s_cnt[8];
    __shared__ float  s_acc[4][EDD];

    const int ba   = blockIdx.x;
    const int b    = ba / AA;
    const int tid  = threadIdx.x;    // 0..127
    const int wrp  = tid >> 5;       // 0..3
    const int lane = tid & 31;

    for (int i = tid; i < NW; i += 128) s_w[i] = g_w[(size_t)ba * NW + i] + b_fc[i];

    if (tid < NCAM * NPT) {
        const float fsx[7] = {0.f, 0.45f, -0.45f, 0.f, 0.f, 0.f, 0.f};
        const float fsy[7] = {0.f, 0.f, 0.f, 0.45f, -0.45f, 0.f, 0.f};
        const float fsz[7] = {0.f, 0.f, 0.f, 0.f, 0.f, 0.45f, -0.45f};
        int cam = tid / NPT, p = tid % NPT;
        const float* an = anchor + (size_t)ba * 8;
        float e0 = expf(an[3]), e1 = expf(an[4]), e2 = expf(an[5]);
        float k0 = fsx[p] * e0, k1 = fsy[p] * e1, k2 = fsz[p] * e2;
        float sn = an[6], cs = an[7];
        float X = cs * k0 - sn * k1 + an[0];
        float Y = sn * k0 + cs * k1 + an[1];
        float Z = k2 + an[2];
        const float* M = proj + (size_t)(b * NCAM + cam) * 16;
        float d0 = M[0] * X + M[1] * Y + M[2]  * Z + M[3];
        float d1 = M[4] * X + M[5] * Y + M[6]  * Z + M[7];
        float d2 = M[8] * X + M[9] * Y + M[10] * Z + M[11];
        float iz = 1.f / fmaxf(d2, 1e-5f);
        float x = d0 * iz / fmaxf(wh[(size_t)(b * NCAM + cam) * 2 + 0], 1e-5f);
        float y = d1 * iz / fmaxf(wh[(size_t)(b * NCAM + cam) * 2 + 1], 1e-5f);
        s_uv[tid][0] = x * 2.f - 1.f;
        s_uv[tid][1] = y * 2.f - 1.f;
    }
    __syncthreads();

    // softmax: warp wrp -> groups wrp*2, wrp*2+1
#pragma unroll
    for (int q = 0; q < 2; q++) {
        int gg = wrp * 2 + q;
        float mx = -INFINITY;
        for (int cc = lane; cc < 168; cc += 32) mx = fmaxf(mx, s_w[cc * 8 + gg]);
#pragma unroll
        for (int o = 16; o; o >>= 1) mx = fmaxf(mx, __shfl_xor_sync(0xffffffffu, mx, o));
        float sum = 0.f;
        for (int cc = lane; cc < 168; cc += 32) {
            float e = expf(s_w[cc * 8 + gg] - mx);
            s_w[cc * 8 + gg] = e;
            sum += e;
        }
#pragma unroll
        for (int o = 16; o; o >>= 1) sum += __shfl_xor_sync(0xffffffffu, sum, o);
        float inv = 1.f / sum;
        for (int cc = lane; cc < 168; cc += 32) s_w[cc * 8 + gg] *= inv;
    }

    // descriptors: 168 over 128 threads, 2 iterations + compaction
    const int Hl[4]  = {64, 32, 16, 8};
    const int Wl[4]  = {176, 88, 44, 22};
    const int HWl[4] = {HW0, HW1, HW2, HW3};
    const int PBl[4] = {PB0, PB1, PB2, PB3};
    int4   dA2[2];
    float4 dW2[2];
    unsigned bal2[2];
    int flags = 0;
#pragma unroll
    for (int it = 0; it < 2; it++) {
        int d = it * 128 + tid;
        int flag = 0;
        if (d < NDESC) {
            int cam = d / (NPT * NLVL);
            int r   = d - cam * (NPT * NLVL);
            int p   = r >> 2;
            int lvl = r & 3;
            float u = s_uv[cam * NPT + p][0];
            float v = s_uv[cam * NPT + p][1];
            const int H = Hl[lvl], W = Wl[lvl];
            float gx = (u + 1.f) * (W * 0.5f) - 0.5f;
            float gy = (v + 1.f) * (H * 0.5f) - 0.5f;
            float x0f = floorf(gx), y0f = floorf(gy);
            float wx1 = gx - x0f, wy1 = gy - y0f;
            bool vx0 = (x0f >= 0.f)       && (x0f <= (float)(W - 1));
            bool vx1 = (x0f + 1.f >= 0.f) && (x0f + 1.f <= (float)(W - 1));
            bool vy0 = (y0f >= 0.f)       && (y0f <= (float)(H - 1));
            bool vy1 = (y0f + 1.f >= 0.f) && (y0f + 1.f <= (float)(H - 1));
            flag = ((vx0 || vx1) && (vy0 || vy1)) ? 1 : 0;
            int x0 = (int)fminf(fmaxf(x0f, 0.f),       (float)(W - 1));
            int x1 = (int)fminf(fmaxf(x0f + 1.f, 0.f), (float)(W - 1));
            int y0 = (int)fminf(fmaxf(y0f, 0.f),       (float)(H - 1));
            int y1 = (int)fminf(fmaxf(y0f + 1.f, 0.f), (float)(H - 1));
            dA2[it].x = PBl[lvl] + (b * NCAM + cam) * HWl[lvl] + y0 * W + x0;
            dA2[it].y = (x1 - x0) * 256;
            dA2[it].z = (y1 - y0) * W * 256;
            dA2[it].w = ((cam * NLVL + lvl) * NPT + p) * NGRP;
            dW2[it].x = (vx0 && vy0) ? (1.f - wx1) * (1.f - wy1) : 0.f;
            dW2[it].y = (vx1 && vy0) ? wx1 * (1.f - wy1)         : 0.f;
            dW2[it].z = (vx0 && vy1) ? (1.f - wx1) * wy1         : 0.f;
            dW2[it].w = (vx1 && vy1) ? wx1 * wy1                 : 0.f;
        }
        bal2[it] = __ballot_sync(0xffffffffu, flag);
        flags |= flag << it;
        if (lane == 0) s_cnt[it * 4 + wrp] = __popc(bal2[it]);
    }
    __syncthreads();

    int pfx[8];
    {
        int run = 0;
#pragma unroll
        for (int i = 0; i < 8; i++) { pfx[i] = run; run += s_cnt[i]; }
    }
    int cnt = pfx[7] + s_cnt[7];
#pragma unroll
    for (int it = 0; it < 2; it++) {
        if ((flags >> it) & 1) {
            int pos = pfx[it * 4 + wrp] + __popc(bal2[it] & ((1u << lane) - 1u));
            s_dA[pos] = dA2[it];
            s_dW[pos] = dW2[it];
        }
    }
    __syncthreads();

    // gather + fuse: lane -> channels lane*8..+7; warp strides desc by 4,
    // manually unrolled 2x (loads for both descriptors issued up front).
    const int g = lane >> 2;
    const __half* chan = g_nhwc + lane * 8;
    float a[8];
#pragma unroll
    for (int q = 0; q < 8; q++) a[q] = 0.f;

    int i = wrp;
    for (; i + 4 < cnt; i += 8) {
        int4 Da = s_dA[i];
        int4 Db = s_dA[i + 4];
        float4 wta = s_dW[i];
        float4 wtb = s_dW[i + 4];
        const __half* bpa = chan + (((size_t)Da.x) << 8);
        const __half* bpb = chan + (((size_t)Db.x) << 8);
        uint4 a00 = *(const uint4*)(bpa);
        uint4 a01 = *(const uint4*)(bpa + Da.y);
        uint4 a10 = *(const uint4*)(bpa + Da.z);
        uint4 a11 = *(const uint4*)(bpa + Da.z + Da.y);
        uint4 b00 = *(const uint4*)(bpb);
        uint4 b01 = *(const uint4*)(bpb + Db.y);
        uint4 b10 = *(const uint4*)(bpb + Db.z);
        uint4 b11 = *(const uint4*)(bpb + Db.z + Db.y);
        float wfa = s_w[Da.w + g];
        float wfb = s_w[Db.w + g];
        const unsigned* pa00 = &a00.x; const unsigned* pa01 = &a01.x;
        const unsigned* pa10 = &a10.x; const unsigned* pa11 = &a11.x;
        const unsigned* pb00 = &b00.x; const unsigned* pb01 = &b01.x;
        const unsigned* pb10 = &b10.x; const unsigned* pb11 = &b11.x;
#pragma unroll
        for (int q = 0; q < 4; q++) {
            float2 v00 = __half22float2(*(const __half2*)&pa00[q]);
            float2 v01 = __half22float2(*(const __half2*)&pa01[q]);
            float2 v10 = __half22float2(*(const __half2*)&pa10[q]);
            float2 v11 = __half22float2(*(const __half2*)&pa11[q]);
            float sx = fmaf(wta.x, v00.x, fmaf(wta.y, v01.x, fmaf(wta.z, v10.x, wta.w * v11.x)));
            float sy = fmaf(wta.x, v00.y, fmaf(wta.y, v01.y, fmaf(wta.z, v10.y, wta.w * v11.y)));
            a[q * 2 + 0] = fmaf(sx, wfa, a[q * 2 + 0]);
            a[q * 2 + 1] = fmaf(sy, wfa, a[q * 2 + 1]);
        }
#pragma unroll
        for (int q = 0; q < 4; q++) {
            float2 v00 = __half22float2(*(const __half2*)&pb00[q]);
            float2 v01 = __half22float2(*(const __half2*)&pb01[q]);
            float2 v10 = __half22float2(*(const __half2*)&pb10[q]);
            float2 v11 = __half22float2(*(const __half2*)&pb11[q]);
            float sx = fmaf(wtb.x, v00.x, fmaf(wtb.y, v01.x, fmaf(wtb.z, v10.x, wtb.w * v11.x)));
            float sy = fmaf(wtb.x, v00.y, fmaf(wtb.y, v01.y, fmaf(wtb.z, v10.y, wtb.w * v11.y)));
            a[q * 2 + 0] = fmaf(sx, wfb, a[q * 2 + 0]);
            a[q * 2 + 1] = fmaf(sy, wfb, a[q * 2 + 1]);
        }
    }
    for (; i < cnt; i += 4) {
        int4 D = s_dA[i];
        float4 wt = s_dW[i];
        const __half* bp = chan + (((size_t)D.x) << 8);
        uint4 r00 = *(const uint4*)(bp);
        uint4 r01 = *(const uint4*)(bp + D.y);
        uint4 r10 = *(const uint4*)(bp + D.z);
        uint4 r11 = *(const uint4*)(bp + D.z + D.y);
        float wf = s_w[D.w + g];
        const unsigned* p00 = &r00.x;
        const unsigned* p01 = &r01.x;
        const unsigned* p10 = &r10.x;
        const unsigned* p11 = &r11.x;
#pragma unroll
        for (int q = 0; q < 4; q++) {
            float2 v00 = __half22float2(*(const __half2*)&p00[q]);
            float2 v01 = __half22float2(*(const __half2*)&p01[q]);
            float2 v10 = __half22float2(*(const __half2*)&p10[q]);
            float2 v11 = __half22float2(*(const __half2*)&p11[q]);
            float sx = fmaf(wt.x, v00.x, fmaf(wt.y, v01.x, fmaf(wt.z, v10.x, wt.w * v11.x)));
            float sy = fmaf(wt.x, v00.y, fmaf(wt.y, v01.y, fmaf(wt.z, v10.y, wt.w * v11.y)));
            a[q * 2 + 0] = fmaf(sx, wf, a[q * 2 + 0]);
            a[q * 2 + 1] = fmaf(sy, wf, a[q * 2 + 1]);
        }
    }
#pragma unroll
    for (int q = 0; q < 8; q++) s_acc[wrp][lane * 8 + q] = a[q];
    __syncthreads();

    // combine 4 warps' partials, store fp16 row-major (2 ch per thread)
    {
        int c = tid * 2;
        float o0 = s_acc[0][c + 0] + s_acc[1][c + 0] + s_acc[2][c + 0] + s_acc[3][c + 0];
        float o1 = s_acc[0][c + 1] + s_acc[1][c + 1] + s_acc[2][c + 1] + s_acc[3][c + 1];
        *(__half2*)(g_fusedH + (size_t)ba * EDD + c) = __floats2half2_rn(o0, o1);
    }
}

// =====================================================================
// Out-projection wmma, smem-staged (R15 verbatim).
// =====================================================================
#define OP_LD 264   // padded half leading dim (multiple of 8)
__global__ void __launch_bounds__(256) outproj_wmma(
    const float* __restrict__ bias, float* __restrict__ out)
{
    __shared__ __align__(16) unsigned char raw[50688];
    __half* sA = (__half*)raw;                  // [32][264]  16896B
    __half* sB = (__half*)(raw + 16896);        // [64][264]  33792B
    float (*smO)[32][72] = (float(*)[32][72])raw;  // epilogue reuse

    const int bx = blockIdx.x;                  // n tile (4)
    const int by = blockIdx.y;                  // m tile (60)
    const int tid = threadIdx.x;

#pragma unroll
    for (int s = 0; s < 4; s++) {
        int id = tid + s * 256;
        int row = id >> 5, c8 = id & 31;
        *(uint4*)&sA[row * OP_LD + c8 * 8] =
            *(const uint4*)(g_fusedH + (size_t)(by * 32 + row) * EDD + c8 * 8);
    }
#pragma unroll
    for (int s = 0; s < 8; s++) {
        int id = tid + s * 256;
        int row = id >> 5, c8 = id & 31;
        *(uint4*)&sB[row * OP_LD + c8 * 8] =
            *(const uint4*)(g_woutH + (size_t)(bx * 64 + row) * EDD + c8 * 8);
    }
    __syncthreads();

    const int wid = tid >> 5;
    const int wk  = wid >> 2;
    const int wm  = (wid >> 1) & 1;
    const int wn  = wid & 1;
    const int m0 = wm * 16;
    const int n0 = wn * 32;

    wmma::fragment<wmma::accumulator, 16, 16, 16, float> cf[2];
#pragma unroll
    for (int j = 0; j < 2; j++) wmma::fill_fragment(cf[j], 0.f);

    for (int k0 = wk * 128; k0 < wk * 128 + 128; k0 += 16) {
        wmma::fragment<wmma::matrix_a, 16, 16, 16, __half, wmma::row_major> af;
        wmma::fragment<wmma::matrix_b, 16, 16, 16, __half, wmma::col_major> bf[2];
        wmma::load_matrix_sync(af, sA + m0 * OP_LD + k0, OP_LD);
#pragma unroll
        for (int j = 0; j < 2; j++)
            wmma::load_matrix_sync(bf[j], sB + (n0 + j * 16) * OP_LD + k0, OP_LD);
#pragma unroll
        for (int j = 0; j < 2; j++)
            wmma::mma_sync(cf[j], af, bf[j], cf[j]);
    }
    __syncthreads();

#pragma unroll
    for (int j = 0; j < 2; j++)
        wmma::store_matrix_sync(&smO[wk][m0][n0 + j * 16], cf[j], 72,
                                wmma::mem_row_major);
    __syncthreads();

    const int c = (tid & 15) * 4;
    const int r0 = tid >> 4;
    float4 bb = *(const float4*)(bias + bx * 64 + c);
#pragma unroll
    for (int rr = 0; rr < 2; rr++) {
        int r = r0 + rr * 16;
        int m = by * 32 + r;
        if (m < NBA) {
            float4 o;
            o.x = smO[0][r][c + 0] + smO[1][r][c + 0] + bb.x;
            o.y = smO[0][r][c + 1] + smO[1][r][c + 1] + bb.y;
            o.z = smO[0][r][c + 2] + smO[1][r][c + 2] + bb.z;
            o.w = smO[0][r][c + 3] + smO[1][r][c + 3] + bb.w;
            *(float4*)(out + (size_t)m * EDD + bx * 64 + c) = o;
        }
    }
}

// =====================================================================
// launch
// =====================================================================
extern "C" void kernel_launch(void* const* d_in, const int* in_sizes, int n_in,
                              void* d_out, int out_size)
{
    const float* inst   = (const float*)d_in[0];
    const float* anchor = (const float*)d_in[1];
    const float* emb    = (const float*)d_in[2];
    const float* f0     = (const float*)d_in[3];
    const float* f1     = (const float*)d_in[4];
    const float* f2     = (const float*)d_in[5];
    const float* f3     = (const float*)d_in[6];
    const float* proj   = (const float*)d_in[7];
    const float* wh     = (const float*)d_in[8];
    const float* w_fc   = (const float*)d_in[9];
    const float* b_fc   = (const float*)d_in[10];
    const float* w_out  = (const float*)d_in[11];
    const float* b_out  = (const float*)d_in[12];
    float* out = (float*)d_out;

    fc_gemm_kernel<<<GEMM_BLKS + WOUT_BLKS, 256>>>(inst, emb, w_fc, w_out);
    conv_kernel<<<CVTOT, 256>>>(f0, f1, f2, f3);
    agg_kernel<<<NBA, 128>>>(anchor, proj, wh, b_fc);
    outproj_wmma<<<dim3(EDD / 64, MPAD / 32), 256>>>(b_out, out);
}

// round 17
// speedup vs baseline: 1.0296x; 1.0296x over previous
#include <cuda_runtime.h>
#include <cuda_fp16.h>
#include <mma.h>
#include <math.h>

using namespace nvcuda;

// ----- problem constants -----
#define BB    2
#define AA    900
#define EDD   256
#define NGRP  8
#define NCAM  6
#define NLVL  4
#define NPT   7
#define NW    1344            // NGRP*NCAM*NLVL*NPT
#define NBA   (BB*AA)         // 1800
#define MPAD  1920
#define NDESC (NCAM*NPT*NLVL) // 168
#define NBC   (BB*NCAM)       // 12

// level geometry
#define HW0 11264
#define HW1 2816
#define HW2 704
#define HW3 176
#define PB0 0
#define PB1 (NBC*HW0)
#define PB2 (PB1 + NBC*HW1)
#define PB3 (PB2 + NBC*HW2)
#define NPIX (PB3 + NBC*HW3)           // 179520

// conversion blocks: per level NBC * pixTiles(64px) * chTiles(4x64)
#define CT0 176
#define CT1 44
#define CT2 11
#define CT3 3
#define CV0 (NBC*CT0*4)
#define CV1 (NBC*CT1*4)
#define CV2 (NBC*CT2*4)
#define CV3 (NBC*CT3*4)
#define CVTOT (CV0+CV1+CV2+CV3)        // 11232

#define GEMM_BLKS ((NW/64) * (MPAD/128))   // 315
#define WOUT_BLKS 64

// ----- scratch (allocation-free: device globals; zero-initialized) -----
__device__ __align__(16) __half g_woutH[EDD * EDD];
__device__ __align__(16) float  g_w[MPAD * NW];
__device__ __align__(16) __half g_fusedH[MPAD * EDD];
__device__ __align__(16) __half g_nhwc[(size_t)NPIX * EDD];

// =====================================================================
// FC GEMM kernel (R15 verbatim): g_w = (inst+emb) @ w_fc^T, fp16 wmma,
// plus w_out fp32->fp16 conversion in tail blocks.
// =====================================================================
__global__ void __launch_bounds__(256) fc_gemm_kernel(
    const float* __restrict__ inst, const float* __restrict__ emb,
    const float* __restrict__ w_fc, const float* __restrict__ w_out)
{
    __shared__ __align__(16) __half sA[128 * 32];
    __shared__ __align__(16) __half sB[64 * 32];
    const int tid = threadIdx.x;

    if (blockIdx.x >= GEMM_BLKS) {
        int j = (blockIdx.x - GEMM_BLKS) * 256 + tid;   // float4 idx
        float4 v = *(const float4*)(w_out + (size_t)j * 4);
        __half2 h0 = __floats2half2_rn(v.x, v.y);
        __half2 h1 = __floats2half2_rn(v.z, v.w);
        uint2 o;
        o.x = *(unsigned*)&h0;
        o.y = *(unsigned*)&h1;
        *(uint2*)(g_woutH + (size_t)j * 4) = o;
        return;
    }

    const int gx = blockIdx.x % (NW / 64);
    const int gy = blockIdx.x / (NW / 64);
    const int bm0 = gy * 128;
    const int bn0 = gx * 64;
    const int wid = tid >> 5;
    const int wm  = wid & 3;
    const int wn  = wid >> 2;
    const int m0 = wm * 32;
    const int n0 = wn * 32;

    wmma::fragment<wmma::accumulator, 16, 16, 16, float> cf[2][2];
#pragma unroll
    for (int i = 0; i < 2; i++)
#pragma unroll
        for (int j = 0; j < 2; j++) wmma::fill_fragment(cf[i][j], 0.f);

    for (int kt = 0; kt < 256; kt += 32) {
#pragma unroll
        for (int s = 0; s < 4; s++) {
            int id = tid + s * 256;
            int row = id >> 3, q = id & 7;
            int m = bm0 + row;
            float4 v = make_float4(0.f, 0.f, 0.f, 0.f);
            if (m < NBA) {
                v = *(const float4*)(inst + (size_t)m * 256 + kt + q * 4);
                float4 w = *(const float4*)(emb + (size_t)m * 256 + kt + q * 4);
                v.x += w.x; v.y += w.y; v.z += w.z; v.w += w.w;
            }
            __half2* d = (__half2*)&sA[row * 32 + q * 4];
            d[0] = __floats2half2_rn(v.x, v.y);
            d[1] = __floats2half2_rn(v.z, v.w);
        }
#pragma unroll
        for (int s = 0; s < 2; s++) {
            int id = tid + s * 256;
            int row = id >> 3, q = id & 7;
            int n = bn0 + row;
            float4 v = *(const float4*)(w_fc + (size_t)n * 256 + kt + q * 4);
            __half2* d = (__half2*)&sB[row * 32 + q * 4];
            d[0] = __floats2half2_rn(v.x, v.y);
            d[1] = __floats2half2_rn(v.z, v.w);
        }
        __syncthreads();

#pragma unroll
        for (int kk = 0; kk < 2; kk++) {
            wmma::fragment<wmma::matrix_a, 16, 16, 16, __half, wmma::row_major> af[2];
            wmma::fragment<wmma::matrix_b, 16, 16, 16, __half, wmma::col_major> bf[2];
#pragma unroll
            for (int i = 0; i < 2; i++)
                wmma::load_matrix_sync(af[i], sA + (m0 + i * 16) * 32 + kk * 16, 32);
#pragma unroll
            for (int j = 0; j < 2; j++)
                wmma::load_matrix_sync(bf[j], sB + (n0 + j * 16) * 32 + kk * 16, 32);
#pragma unroll
            for (int i = 0; i < 2; i++)
#pragma unroll
                for (int j = 0; j < 2; j++)
                    wmma::mma_sync(cf[i][j], af[i], bf[j], cf[i][j]);
        }
        __syncthreads();
    }
#pragma unroll
    for (int i = 0; i < 2; i++)
#pragma unroll
        for (int j = 0; j < 2; j++)
            wmma::store_matrix_sync(g_w + (size_t)(bm0 + m0 + i * 16) * NW + bn0 + n0 + j * 16,
                                    cf[i][j], NW, wmma::mem_row_major);
}

// =====================================================================
// Conversion kernel (R15/R10 verbatim): NCHW fp32 -> NHWC fp16,
// 64ch x 64px tile per block, 256 threads.
// =====================================================================
__global__ void __launch_bounds__(256) conv_kernel(
    const float* __restrict__ f0, const float* __restrict__ f1,
    const float* __restrict__ f2, const float* __restrict__ f3)
{
    __shared__ float t[64][65];
    const int tid = threadIdx.x;

    int cb = blockIdx.x;
    const float* fin; int HWl, tilesHW, pbase;
    if (cb < CV0)               { fin = f0; HWl = HW0; tilesHW = CT0; pbase = PB0; }
    else if ((cb -= CV0) < CV1) { fin = f1; HWl = HW1; tilesHW = CT1; pbase = PB1; }
    else if ((cb -= CV1) < CV2) { fin = f2; HWl = HW2; tilesHW = CT2; pbase = PB2; }
    else       { cb -= CV2;       fin = f3; HWl = HW3; tilesHW = CT3; pbase = PB3; }
    const int nt  = tilesHW * 4;
    const int bc  = cb / nt;
    const int r   = cb % nt;
    const int hw0 = (r >> 2) * 64;
    const int c0  = (r & 3) * 64;

    const float* ip = fin + (size_t)bc * 256 * HWl;
#pragma unroll
    for (int s = 0; s < 4; s++) {
        int id = tid + s * 256;
        int row = id >> 4, q = id & 15;
        int hw = hw0 + q * 4;
        if (hw < HWl) {
            float4 v = __ldcs((const float4*)(ip + (size_t)(c0 + row) * HWl + hw));
            t[row][q * 4 + 0] = v.x;
            t[row][q * 4 + 1] = v.y;
            t[row][q * 4 + 2] = v.z;
            t[row][q * 4 + 3] = v.w;
        }
    }
    __syncthreads();
    __half* op = g_nhwc + ((size_t)(pbase + bc * HWl)) * 256;
#pragma unroll
    for (int s = 0; s < 4; s++) {
        int id = tid + s * 256;
        int px = id >> 4, qc = id & 15;
        int hw = hw0 + px;
        if (hw < HWl) {
            __half2 h0 = __floats2half2_rn(t[qc * 4 + 0][px], t[qc * 4 + 1][px]);
            __half2 h1 = __floats2half2_rn(t[qc * 4 + 2][px], t[qc * 4 + 3][px]);
            uint2 o;
            o.x = *(unsigned*)&h0;
            o.y = *(unsigned*)&h1;
            *(uint2*)(op + (size_t)hw * 256 + c0 + qc * 4) = o;
        }
    }
}

// =====================================================================
// Fused aggregation: 64 threads (R15 shape); lane covers 8 channels
// (uint4 gathers); two warps split the descriptor list; gather loop
// manually unrolled 2x (loads for i and i+2 issued up front -> MLP 8).
// =====================================================================
__global__ void __launch_bounds__(64) agg_kernel(
    const float* __restrict__ anchor, const float* __restrict__ proj,
    const float* __restrict__ wh, const float* __restrict__ b_fc)
{
    __shared__ float  s_w[NW];
    __shared__ float  s_uv[NCAM * NPT][2];
    __shared__ int4   s_dA[NDESC];
    __shared__ float4 s_dW[NDESC];
    __shared__ int    s_cnt[6];
    __shared__ float  s_acc[2][EDD];

    const int ba   = blockIdx.x;
    const int b    = ba / AA;
    const int tid  = threadIdx.x;
    const int wrp  = tid >> 5;
    const int lane = tid & 31;

    for (int i = tid; i < NW; i += 64) s_w[i] = g_w[(size_t)ba * NW + i] + b_fc[i];

    if (tid < NCAM * NPT) {
        const float fsx[7] = {0.f, 0.45f, -0.45f, 0.f, 0.f, 0.f, 0.f};
        const float fsy[7] = {0.f, 0.f, 0.f, 0.45f, -0.45f, 0.f, 0.f};
        const float fsz[7] = {0.f, 0.f, 0.f, 0.f, 0.f, 0.45f, -0.45f};
        int cam = tid / NPT, p = tid % NPT;
        const float* an = anchor + (size_t)ba * 8;
        float e0 = expf(an[3]), e1 = expf(an[4]), e2 = expf(an[5]);
        float k0 = fsx[p] * e0, k1 = fsy[p] * e1, k2 = fsz[p] * e2;
        float sn = an[6], cs = an[7];
        float X = cs * k0 - sn * k1 + an[0];
        float Y = sn * k0 + cs * k1 + an[1];
        float Z = k2 + an[2];
        const float* M = proj + (size_t)(b * NCAM + cam) * 16;
        float d0 = M[0] * X + M[1] * Y + M[2]  * Z + M[3];
        float d1 = M[4] * X + M[5] * Y + M[6]  * Z + M[7];
        float d2 = M[8] * X + M[9] * Y + M[10] * Z + M[11];
        float iz = 1.f / fmaxf(d2, 1e-5f);
        float x = d0 * iz / fmaxf(wh[(size_t)(b * NCAM + cam) * 2 + 0], 1e-5f);
        float y = d1 * iz / fmaxf(wh[(size_t)(b * NCAM + cam) * 2 + 1], 1e-5f);
        s_uv[tid][0] = x * 2.f - 1.f;
        s_uv[tid][1] = y * 2.f - 1.f;
    }
    __syncthreads();

#pragma unroll
    for (int q = 0; q < 4; q++) {
        int gg = wrp * 4 + q;
        float mx = -INFINITY;
        for (int cc = lane; cc < 168; cc += 32) mx = fmaxf(mx, s_w[cc * 8 + gg]);
#pragma unroll
        for (int o = 16; o; o >>= 1) mx = fmaxf(mx, __shfl_xor_sync(0xffffffffu, mx, o));
        float sum = 0.f;
        for (int cc = lane; cc < 168; cc += 32) {
            float e = expf(s_w[cc * 8 + gg] - mx);
            s_w[cc * 8 + gg] = e;
            sum += e;
        }
#pragma unroll
        for (int o = 16; o; o >>= 1) sum += __shfl_xor_sync(0xffffffffu, sum, o);
        float inv = 1.f / sum;
        for (int cc = lane; cc < 168; cc += 32) s_w[cc * 8 + gg] *= inv;
    }

    const int Hl[4]  = {64, 32, 16, 8};
    const int Wl[4]  = {176, 88, 44, 22};
    const int HWl[4] = {HW0, HW1, HW2, HW3};
    const int PBl[4] = {PB0, PB1, PB2, PB3};
    int4   dA3[3];
    float4 dW3[3];
    unsigned bal3[3];
    int flags = 0;
#pragma unroll
    for (int it = 0; it < 3; it++) {
        int d = it * 64 + tid;
        int flag = 0;
        if (d < NDESC) {
            int cam = d / (NPT * NLVL);
            int r   = d - cam * (NPT * NLVL);
            int p   = r >> 2;
            int lvl = r & 3;
            float u = s_uv[cam * NPT + p][0];
            float v = s_uv[cam * NPT + p][1];
            const int H = Hl[lvl], W = Wl[lvl];
            float gx = (u + 1.f) * (W * 0.5f) - 0.5f;
            float gy = (v + 1.f) * (H * 0.5f) - 0.5f;
            float x0f = floorf(gx), y0f = floorf(gy);
            float wx1 = gx - x0f, wy1 = gy - y0f;
            bool vx0 = (x0f >= 0.f)       && (x0f <= (float)(W - 1));
            bool vx1 = (x0f + 1.f >= 0.f) && (x0f + 1.f <= (float)(W - 1));
            bool vy0 = (y0f >= 0.f)       && (y0f <= (float)(H - 1));
            bool vy1 = (y0f + 1.f >= 0.f) && (y0f + 1.f <= (float)(H - 1));
            flag = ((vx0 || vx1) && (vy0 || vy1)) ? 1 : 0;
            int x0 = (int)fminf(fmaxf(x0f, 0.f),       (float)(W - 1));
            int x1 = (int)fminf(fmaxf(x0f + 1.f, 0.f), (float)(W - 1));
            int y0 = (int)fminf(fmaxf(y0f, 0.f),       (float)(H - 1));
            int y1 = (int)fminf(fmaxf(y0f + 1.f, 0.f), (float)(H - 1));
            dA3[it].x = PBl[lvl] + (b * NCAM + cam) * HWl[lvl] + y0 * W + x0;
            dA3[it].y = (x1 - x0) * 256;
            dA3[it].z = (y1 - y0) * W * 256;
            dA3[it].w = ((cam * NLVL + lvl) * NPT + p) * NGRP;
            dW3[it].x = (vx0 && vy0) ? (1.f - wx1) * (1.f - wy1) : 0.f;
            dW3[it].y = (vx1 && vy0) ? wx1 * (1.f - wy1)         : 0.f;
            dW3[it].z = (vx0 && vy1) ? (1.f - wx1) * wy1         : 0.f;
            dW3[it].w = (vx1 && vy1) ? wx1 * wy1                 : 0.f;
        }
        bal3[it] = __ballot_sync(0xffffffffu, flag);
        flags |= flag << it;
        if (lane == 0) s_cnt[it * 2 + wrp] = __popc(bal3[it]);
    }
    __syncthreads();

    int pfx[6];
    {
        int run = 0;
#pragma unroll
        for (int i = 0; i < 6; i++) { pfx[i] = run; run += s_cnt[i]; }
    }
    int cnt = pfx[5] + s_cnt[5];
#pragma unroll
    for (int it = 0; it < 3; it++) {
        if ((flags >> it) & 1) {
            int pos = pfx[it * 2 + wrp] + __popc(bal3[it] & ((1u << lane) - 1u));
            s_dA[pos] = dA3[it];
            s_dW[pos] = dW3[it];
        }
    }
    __syncthreads();

    const int g = lane >> 2;
    const __half* chan = g_nhwc + lane * 8;
    float a[8];
#pragma unroll
    for (int q = 0; q < 8; q++) a[q] = 0.f;

    // 2-deep unrolled gather: descriptors i and i+2 loaded up front.
    int i = wrp;
    for (; i + 2 < cnt; i += 4) {
        int4 Da = s_dA[i];
        int4 Db = s_dA[i + 2];
        float4 wta = s_dW[i];
        float4 wtb = s_dW[i + 2];
        const __half* bpa = chan + (((size_t)Da.x) << 8);
        const __half* bpb = chan + (((size_t)Db.x) << 8);
        uint4 a00 = *(const uint4*)(bpa);
        uint4 a01 = *(const uint4*)(bpa + Da.y);
        uint4 a10 = *(const uint4*)(bpa + Da.z);
        uint4 a11 = *(const uint4*)(bpa + Da.z + Da.y);
        uint4 b00 = *(const uint4*)(bpb);
        uint4 b01 = *(const uint4*)(bpb + Db.y);
        uint4 b10 = *(const uint4*)(bpb + Db.z);
        uint4 b11 = *(const uint4*)(bpb + Db.z + Db.y);
        float wfa = s_w[Da.w + g];
        float wfb = s_w[Db.w + g];
        const unsigned* pa00 = &a00.x; const unsigned* pa01 = &a01.x;
        const unsigned* pa10 = &a10.x; const unsigned* pa11 = &a11.x;
        const unsigned* pb00 = &b00.x; const unsigned* pb01 = &b01.x;
        const unsigned* pb10 = &b10.x; const unsigned* pb11 = &b11.x;
#pragma unroll
        for (int q = 0; q < 4; q++) {
            float2 v00 = __half22float2(*(const __half2*)&pa00[q]);
            float2 v01 = __half22float2(*(const __half2*)&pa01[q]);
            float2 v10 = __half22float2(*(const __half2*)&pa10[q]);
            float2 v11 = __half22float2(*(const __half2*)&pa11[q]);
            float sx = fmaf(wta.x, v00.x, fmaf(wta.y, v01.x, fmaf(wta.z, v10.x, wta.w * v11.x)));
            float sy = fmaf(wta.x, v00.y, fmaf(wta.y, v01.y, fmaf(wta.z, v10.y, wta.w * v11.y)));
            a[q * 2 + 0] = fmaf(sx, wfa, a[q * 2 + 0]);
            a[q * 2 + 1] = fmaf(sy, wfa, a[q * 2 + 1]);
        }
#pragma unroll
        for (int q = 0; q < 4; q++) {
            float2 v00 = __half22float2(*(const __half2*)&pb00[q]);
            float2 v01 = __half22float2(*(const __half2*)&pb01[q]);
            float2 v10 = __half22float2(*(const __half2*)&pb10[q]);
            float2 v11 = __half22float2(*(const __half2*)&pb11[q]);
            float sx = fmaf(wtb.x, v00.x, fmaf(wtb.y, v01.x, fmaf(wtb.z, v10.x, wtb.w * v11.x)));
            float sy = fmaf(wtb.x, v00.y, fmaf(wtb.y, v01.y, fmaf(wtb.z, v10.y, wtb.w * v11.y)));
            a[q * 2 + 0] = fmaf(sx, wfb, a[q * 2 + 0]);
            a[q * 2 + 1] = fmaf(sy, wfb, a[q * 2 + 1]);
        }
    }
    for (; i < cnt; i += 2) {
        int4 D = s_dA[i];
        float4 wt = s_dW[i];
        const __half* bp = chan + (((size_t)D.x) << 8);
        uint4 r00 = *(const uint4*)(bp);
        uint4 r01 = *(const uint4*)(bp + D.y);
        uint4 r10 = *(const uint4*)(bp + D.z);
        uint4 r11 = *(const uint4*)(bp + D.z + D.y);
        float wf = s_w[D.w + g];
        const unsigned* p00 = &r00.x;
        const unsigned* p01 = &r01.x;
        const unsigned* p10 = &r10.x;
        const unsigned* p11 = &r11.x;
#pragma unroll
        for (int q = 0; q < 4; q++) {
            float2 v00 = __half22float2(*(const __half2*)&p00[q]);
            float2 v01 = __half22float2(*(const __half2*)&p01[q]);
            float2 v10 = __half22float2(*(const __half2*)&p10[q]);
            float2 v11 = __half22float2(*(const __half2*)&p11[q]);
            float sx = fmaf(wt.x, v00.x, fmaf(wt.y, v01.x, fmaf(wt.z, v10.x, wt.w * v11.x)));
            float sy = fmaf(wt.x, v00.y, fmaf(wt.y, v01.y, fmaf(wt.z, v10.y, wt.w * v11.y)));
            a[q * 2 + 0] = fmaf(sx, wf, a[q * 2 + 0]);
            a[q * 2 + 1] = fmaf(sy, wf, a[q * 2 + 1]);
        }
    }
#pragma unroll
    for (int q = 0; q < 8; q++) s_acc[wrp][lane * 8 + q] = a[q];
    __syncthreads();

    {
        int c = tid * 4;
        float o0 = s_acc[0][c + 0] + s_acc[1][c + 0];
        float o1 = s_acc[0][c + 1] + s_acc[1][c + 1];
        float o2 = s_acc[0][c + 2] + s_acc[1][c + 2];
        float o3 = s_acc[0][c + 3] + s_acc[1][c + 3];
        __half2* fp = (__half2*)(g_fusedH + (size_t)ba * EDD + c);
        fp[0] = __floats2half2_rn(o0, o1);
        fp[1] = __floats2half2_rn(o2, o3);
    }
}

// =====================================================================
// Out-projection wmma, smem-staged (R15 verbatim).
// =====================================================================
#define OP_LD 264   // padded half leading dim (multiple of 8)
__global__ void __launch_bounds__(256) outproj_wmma(
    const float* __restrict__ bias, float* __restrict__ out)
{
    __shared__ __align__(16) unsigned char raw[50688];
    __half* sA = (__half*)raw;                  // [32][264]  16896B
    __half* sB = (__half*)(raw + 16896);        // [64][264]  33792B
    float (*smO)[32][72] = (float(*)[32][72])raw;  // epilogue reuse

    const int bx = blockIdx.x;                  // n tile (4)
    const int by = blockIdx.y;                  // m tile (60)
    const int tid = threadIdx.x;

#pragma unroll
    for (int s = 0; s < 4; s++) {
        int id = tid + s * 256;
        int row = id >> 5, c8 = id & 31;
        *(uint4*)&sA[row * OP_LD + c8 * 8] =
            *(const uint4*)(g_fusedH + (size_t)(by * 32 + row) * EDD + c8 * 8);
    }
#pragma unroll
    for (int s = 0; s < 8; s++) {
        int id = tid + s * 256;
        int row = id >> 5, c8 = id & 31;
        *(uint4*)&sB[row * OP_LD + c8 * 8] =
            *(const uint4*)(g_woutH + (size_t)(bx * 64 + row) * EDD + c8 * 8);
    }
    __syncthreads();

    const int wid = tid >> 5;
    const int wk  = wid >> 2;
    const int wm  = (wid >> 1) & 1;
    const int wn  = wid & 1;
    const int m0 = wm * 16;
    const int n0 = wn * 32;

    wmma::fragment<wmma::accumulator, 16, 16, 16, float> cf[2];
#pragma unroll
    for (int j = 0; j < 2; j++) wmma::fill_fragment(cf[j], 0.f);

    for (int k0 = wk * 128; k0 < wk * 128 + 128; k0 += 16) {
        wmma::fragment<wmma::matrix_a, 16, 16, 16, __half, wmma::row_major> af;
        wmma::fragment<wmma::matrix_b, 16, 16, 16, __half, wmma::col_major> bf[2];
        wmma::load_matrix_sync(af, sA + m0 * OP_LD + k0, OP_LD);
#pragma unroll
        for (int j = 0; j < 2; j++)
            wmma::load_matrix_sync(bf[j], sB + (n0 + j * 16) * OP_LD + k0, OP_LD);
#pragma unroll
        for (int j = 0; j < 2; j++)
            wmma::mma_sync(cf[j], af, bf[j], cf[j]);
    }
    __syncthreads();

#pragma unroll
    for (int j = 0; j < 2; j++)
        wmma::store_matrix_sync(&smO[wk][m0][n0 + j * 16], cf[j], 72,
                                wmma::mem_row_major);
    __syncthreads();

    const int c = (tid & 15) * 4;
    const int r0 = tid >> 4;
    float4 bb = *(const float4*)(bias + bx * 64 + c);
#pragma unroll
    for (int rr = 0; rr < 2; rr++) {
        int r = r0 + rr * 16;
        int m = by * 32 + r;
        if (m < NBA) {
            float4 o;
            o.x = smO[0][r][c + 0] + smO[1][r][c + 0] + bb.x;
            o.y = smO[0][r][c + 1] + smO[1][r][c + 1] + bb.y;
            o.z = smO[0][r][c + 2] + smO[1][r][c + 2] + bb.z;
            o.w = smO[0][r][c + 3] + smO[1][r][c + 3] + bb.w;
            *(float4*)(out + (size_t)m * EDD + bx * 64 + c) = o;
        }
    }
}

// =====================================================================
// launch
// =====================================================================
extern "C" void kernel_launch(void* const* d_in, const int* in_sizes, int n_in,
                              void* d_out, int out_size)
{
    const float* inst   = (const float*)d_in[0];
    const float* anchor = (const float*)d_in[1];
    const float* emb    = (const float*)d_in[2];
    const float* f0     = (const float*)d_in[3];
    const float* f1     = (const float*)d_in[4];
    const float* f2     = (const float*)d_in[5];
    const float* f3     = (const float*)d_in[6];
    const float* proj   = (const float*)d_in[7];
    const float* wh     = (const float*)d_in[8];
    const float* w_fc   = (const float*)d_in[9];
    const float* b_fc   = (const float*)d_in[10];
    const float* w_out  = (const float*)d_in[11];
    const float* b_out  = (const float*)d_in[12];
    float* out = (float*)d_out;

    fc_gemm_kernel<<<GEMM_BLKS + WOUT_BLKS, 256>>>(inst, emb, w_fc, w_out);
    conv_kernel<<<CVTOT, 256>>>(f0, f1, f2, f3);
    agg_kernel<<<NBA, 64>>>(anchor, proj, wh, b_fc);
    outproj_wmma<<<dim3(EDD / 64, MPAD / 32), 256>>>(b_out, out);
}